// round 12
// baseline (speedup 1.0000x reference)
#include <cuda_runtime.h>
#include <stdint.h>
#include <math.h>

#define BATCH  256
#define NPTS   16384
#define CHUNKS 2
#define GRP_PER_CHUNK (NPTS / 4 / CHUNKS)   // 2048 groups of 4 points
#define THREADS 256

// scratch: partial sums, counters, flags, solved transforms
__device__ float g_part[BATCH][CHUNKS][16];
__device__ unsigned g_cnt[BATCH];   // arrival counter (reset by solver)
__device__ unsigned g_done[BATCH];  // rt-ready flag  (reset by last finisher)
__device__ unsigned g_fin[BATCH];   // finish counter (reset by last finisher)
__device__ float g_rt[BATCH][16];

// ---------------------------------------------------------------------------
// FP32 3x3 Kabsch solve
// ---------------------------------------------------------------------------
__device__ __forceinline__ float nrsqrt(float s) {
    float n = rsqrtf(s);
    return n * (1.5f - 0.5f * s * n * n);
}

__device__ __forceinline__ void jrotf(float S[3][3], float V[3][3], int p, int q) {
    float apq = S[p][q];
    if (fabsf(apq) < 1e-30f) return;
    float theta = (S[q][q] - S[p][p]) / (2.0f * apq);
    float t = copysignf(1.0f, theta) / (fabsf(theta) + sqrtf(theta * theta + 1.0f));
    float c = nrsqrt(t * t + 1.0f);
    float s = t * c;
    int r = 3 - p - q;
    float Spp = S[p][p], Sqq = S[q][q];
    S[p][p] = Spp - t * apq;
    S[q][q] = Sqq + t * apq;
    S[p][q] = S[q][p] = 0.0f;
    float Srp = S[r][p], Srq = S[r][q];
    S[r][p] = S[p][r] = c * Srp - s * Srq;
    S[r][q] = S[q][r] = s * Srp + c * Srq;
#pragma unroll
    for (int i = 0; i < 3; i++) {
        float vp = V[i][p], vq = V[i][q];
        V[i][p] = c * vp - s * vq;
        V[i][q] = s * vp + c * vq;
    }
}

__device__ void kabsch_solve(const float* sums, float* rt) {
    float W = sums[0];
    float invW = 1.0f / W;
    float Swp[3] = {sums[1], sums[2], sums[3]};
    float Swt[3] = {sums[4], sums[5], sums[6]};

    float A[3][3];
#pragma unroll
    for (int i = 0; i < 3; i++)
#pragma unroll
        for (int j = 0; j < 3; j++)
            A[i][j] = sums[7 + 3 * i + j] - Swt[i] * Swp[j] * invW;

    float S[3][3];
#pragma unroll
    for (int j = 0; j < 3; j++)
#pragma unroll
        for (int k = 0; k < 3; k++)
            S[j][k] = A[0][j] * A[0][k] + A[1][j] * A[1][k] + A[2][j] * A[2][k];

    float V[3][3] = {{1,0,0},{0,1,0},{0,0,1}};
#pragma unroll
    for (int sweep = 0; sweep < 12; sweep++) {
        jrotf(S, V, 0, 1);
        jrotf(S, V, 0, 2);
        jrotf(S, V, 1, 2);
    }

    float d[3] = {S[0][0], S[1][1], S[2][2]};
    int id[3] = {0, 1, 2};
    if (d[id[0]] < d[id[1]]) { int t = id[0]; id[0] = id[1]; id[1] = t; }
    if (d[id[0]] < d[id[2]]) { int t = id[0]; id[0] = id[2]; id[2] = t; }
    if (d[id[1]] < d[id[2]]) { int t = id[1]; id[1] = id[2]; id[2] = t; }

    float v1[3], v2[3], v3[3];
#pragma unroll
    for (int i = 0; i < 3; i++) { v1[i] = V[i][id[0]]; v2[i] = V[i][id[1]]; v3[i] = V[i][id[2]]; }

    float u1[3], u2[3];
#pragma unroll
    for (int i = 0; i < 3; i++) u1[i] = A[i][0]*v1[0] + A[i][1]*v1[1] + A[i][2]*v1[2];
    float n1 = nrsqrt(u1[0]*u1[0] + u1[1]*u1[1] + u1[2]*u1[2] + 1e-37f);
#pragma unroll
    for (int i = 0; i < 3; i++) u1[i] *= n1;
#pragma unroll
    for (int i = 0; i < 3; i++) u2[i] = A[i][0]*v2[0] + A[i][1]*v2[1] + A[i][2]*v2[2];
    float dp = u2[0]*u1[0] + u2[1]*u1[1] + u2[2]*u1[2];
#pragma unroll
    for (int i = 0; i < 3; i++) u2[i] -= dp * u1[i];
    float n2 = nrsqrt(u2[0]*u2[0] + u2[1]*u2[1] + u2[2]*u2[2] + 1e-37f);
#pragma unroll
    for (int i = 0; i < 3; i++) u2[i] *= n2;

    float detraw = v1[0]*(v2[1]*v3[2] - v2[2]*v3[1])
                 - v1[1]*(v2[0]*v3[2] - v2[2]*v3[0])
                 + v1[2]*(v2[0]*v3[1] - v2[1]*v3[0]);
    float detV = (detraw >= 0.0f) ? 1.0f : -1.0f;
    float u3[3] = {
        detV * (u1[1]*u2[2] - u1[2]*u2[1]),
        detV * (u1[2]*u2[0] - u1[0]*u2[2]),
        detV * (u1[0]*u2[1] - u1[1]*u2[0])
    };

#pragma unroll
    for (int i = 0; i < 3; i++)
#pragma unroll
        for (int j = 0; j < 3; j++)
            rt[3*i + j] = u1[i]*v1[j] + u2[i]*v2[j] + u3[i]*v3[j];
#pragma unroll
    for (int j = 0; j < 3; j++) rt[9  + j] = Swp[j] * invW;
#pragma unroll
    for (int i = 0; i < 3; i++) rt[12 + i] = Swt[i] * invW;
}

// ---------------------------------------------------------------------------
// Fused single kernel: 512 blocks (2 sibling chunk-blocks per batch, adjacent
// bids). Reduce own chunk -> last sibling solves + publishes -> spin (same-
// batch siblings only, co-resident in wave 1) -> apply own chunk with pred/
// mask re-read from a HOT L2 (the re-read happens microseconds after the
// first read). Flags/counters reset in-kernel for graph-replay determinism.
// ---------------------------------------------------------------------------
__global__ void __launch_bounds__(THREADS, 4) wra_fused(
    const float* __restrict__ pred,
    const float* __restrict__ truec,
    const float* __restrict__ wts,
    const uint32_t* __restrict__ mask,
    float* __restrict__ out)
{
    const int b = blockIdx.x >> 1;
    const int chunk = blockIdx.x & 1;
    const float4* __restrict__ p4 = reinterpret_cast<const float4*>(pred  + (size_t)b * NPTS * 3);
    const float4* __restrict__ t4 = reinterpret_cast<const float4*>(truec + (size_t)b * NPTS * 3);
    const float4* __restrict__ w4 = reinterpret_cast<const float4*>(wts   + (size_t)b * NPTS);
    const uint4* __restrict__ m4  = reinterpret_cast<const uint4*>(mask + (size_t)b * NPTS);

    float acc[16];
#pragma unroll
    for (int i = 0; i < 16; i++) acc[i] = 0.f;

    const int g0 = chunk * GRP_PER_CHUNK;
    // -------- Phase 1: reduce own chunk ------------------------------------
#pragma unroll
    for (int it = 0; it < GRP_PER_CHUNK / THREADS; it++) {
        const int g = g0 + it * THREADS + threadIdx.x;
        float4 a0 = __ldg(&p4[3*g+0]), a1 = __ldg(&p4[3*g+1]), a2 = __ldg(&p4[3*g+2]);
        float4 c0 = __ldcs(&t4[3*g+0]), c1 = __ldcs(&t4[3*g+1]), c2 = __ldcs(&t4[3*g+2]);
        float4 wv = __ldcs(&w4[g]);
        uint4  mv = __ldg(&m4[g]);

        float px[4] = {a0.x, a0.w, a1.z, a2.y};
        float py[4] = {a0.y, a1.x, a1.w, a2.z};
        float pz[4] = {a0.z, a1.y, a2.x, a2.w};
        float tx[4] = {c0.x, c0.w, c1.z, c2.y};
        float ty[4] = {c0.y, c1.x, c1.w, c2.z};
        float tz[4] = {c0.z, c1.y, c2.x, c2.w};
        float ww[4] = {wv.x, wv.y, wv.z, wv.w};
        uint32_t mm[4] = {mv.x, mv.y, mv.z, mv.w};

#pragma unroll
        for (int k = 0; k < 4; k++) {
            float wi = (mm[k] != 0u) ? ww[k] : 0.f;
            float wtx = wi * tx[k], wty = wi * ty[k], wtz = wi * tz[k];
            acc[0]  += wi;
            acc[1]  += wi * px[k];
            acc[2]  += wi * py[k];
            acc[3]  += wi * pz[k];
            acc[4]  += wtx;
            acc[5]  += wty;
            acc[6]  += wtz;
            acc[7]  += wtx * px[k];
            acc[8]  += wtx * py[k];
            acc[9]  += wtx * pz[k];
            acc[10] += wty * px[k];
            acc[11] += wty * py[k];
            acc[12] += wty * pz[k];
            acc[13] += wtz * px[k];
            acc[14] += wtz * py[k];
            acc[15] += wtz * pz[k];
        }
    }

#pragma unroll
    for (int i = 0; i < 16; i++) {
#pragma unroll
        for (int o = 16; o > 0; o >>= 1)
            acc[i] += __shfl_down_sync(0xffffffffu, acc[i], o);
    }

    __shared__ float sh[THREADS / 32][16];
    __shared__ float prm[15];
    const int warp = threadIdx.x >> 5, lane = threadIdx.x & 31;
    if (lane == 0) {
#pragma unroll
        for (int i = 0; i < 16; i++) sh[warp][i] = acc[i];
    }
    __syncthreads();
    if (threadIdx.x < 16) {
        float s = 0.f;
#pragma unroll
        for (int w = 0; w < THREADS / 32; w++) s += sh[w][threadIdx.x];
        g_part[b][chunk][threadIdx.x] = s;
    }
    __syncthreads();

    // -------- Phase 2: last sibling solves; everyone waits on g_done[b] -----
    if (threadIdx.x == 0) {
        __threadfence();
        unsigned prev = atomicAdd(&g_cnt[b], 1u);
        if (prev == CHUNKS - 1) {
            __threadfence();
            float sums[16];
#pragma unroll
            for (int i = 0; i < 16; i++) {
                float s = 0.f;
#pragma unroll
                for (int c = 0; c < CHUNKS; c++) s += g_part[b][c][i];
                sums[i] = s;
            }
            float rt[15];
            kabsch_solve(sums, rt);
#pragma unroll
            for (int i = 0; i < 15; i++) g_rt[b][i] = rt[i];
            g_cnt[b] = 0u;                       // reset for next replay
            __threadfence();                     // publish rt before flag
            atomicExch(&g_done[b], 1u);          // release
        } else {
            // spin until sibling publishes (co-resident: bids adjacent, all
            // 512 blocks fit in one wave)
            while (atomicAdd(&g_done[b], 0u) == 0u) __nanosleep(128);
        }
        __threadfence();                         // acquire rt
    }
    __syncthreads();
    if (threadIdx.x < 15) prm[threadIdx.x] = g_rt[b][threadIdx.x];
    __syncthreads();

    const float r00 = prm[0], r01 = prm[1], r02 = prm[2];
    const float r10 = prm[3], r11 = prm[4], r12 = prm[5];
    const float r20 = prm[6], r21 = prm[7], r22 = prm[8];
    const float pc0 = prm[9], pc1 = prm[10], pc2 = prm[11];
    const float tc0 = prm[12], tc1 = prm[13], tc2 = prm[14];

    // -------- Phase 3: apply own chunk (pred/mask re-read hits hot L2) ------
    float4* __restrict__ o4 = reinterpret_cast<float4*>(out + (size_t)b * NPTS * 3);
#pragma unroll 2
    for (int it = 0; it < GRP_PER_CHUNK / THREADS; it++) {
        const int g = g0 + it * THREADS + threadIdx.x;
        float4 a0 = __ldg(&p4[3*g+0]), a1 = __ldg(&p4[3*g+1]), a2 = __ldg(&p4[3*g+2]);
        uint4  mv = __ldg(&m4[g]);

        float px[4] = {a0.x, a0.w, a1.z, a2.y};
        float py[4] = {a0.y, a1.x, a1.w, a2.z};
        float pz[4] = {a0.z, a1.y, a2.x, a2.w};
        uint32_t mm[4] = {mv.x, mv.y, mv.z, mv.w};
        float ox[4], oy[4], oz[4];
#pragma unroll
        for (int k = 0; k < 4; k++) {
            bool mk = (mm[k] != 0u);
            float cx = (mk ? px[k] : 0.f) - pc0;
            float cy = (mk ? py[k] : 0.f) - pc1;
            float cz = (mk ? pz[k] : 0.f) - pc2;
            ox[k] = cx * r00 + cy * r10 + cz * r20 + tc0;
            oy[k] = cx * r01 + cy * r11 + cz * r21 + tc1;
            oz[k] = cx * r02 + cy * r12 + cz * r22 + tc2;
        }
        float4 o0 = {ox[0], oy[0], oz[0], ox[1]};
        float4 o1 = {oy[1], oz[1], ox[2], oy[2]};
        float4 o2 = {oz[2], ox[3], oy[3], oz[3]};
        __stcs(&o4[3*g+0], o0);
        __stcs(&o4[3*g+1], o1);
        __stcs(&o4[3*g+2], o2);
    }

    // -------- Phase 4: reset flags for next graph replay --------------------
    if (threadIdx.x == 0) {
        __threadfence();
        unsigned prev = atomicAdd(&g_fin[b], 1u);
        if (prev == CHUNKS - 1) {
            g_done[b] = 0u;
            g_fin[b]  = 0u;
        }
    }
}

// ---------------------------------------------------------------------------
extern "C" void kernel_launch(void* const* d_in, const int* in_sizes, int n_in,
                              void* d_out, int out_size) {
    const float*    pred  = (const float*)d_in[0];
    const float*    truec = (const float*)d_in[1];
    const float*    wts   = (const float*)d_in[2];
    const uint32_t* mask  = (const uint32_t*)d_in[3];
    float* out = (float*)d_out;

    wra_fused<<<BATCH * CHUNKS, THREADS>>>(pred, truec, wts, mask, out);
}